// round 1
// baseline (speedup 1.0000x reference)
#include <cuda_runtime.h>
#include <math.h>

#define NB    512
#define NNOI  100
#define NC    10
#define NEMB  50
#define CIN1  306      // 256 + NEMB
#define C1    256
#define C2    128
#define LRA   0.3f
#define BN_EPS 1e-3f

// scratch (static device globals; no runtime allocation)
__device__ float g_x2[(size_t)NB * 49 * CIN1];   // [b][pos=7*7][ci]
__device__ float g_h1[(size_t)NB * 49 * C1];     // [b][pos][co]
__device__ float g_h2[(size_t)NB * 196 * C2];    // [b][oy14][ox14][co]

__device__ __forceinline__ float lrelu(float x) { return x >= 0.f ? x : LRA * x; }

// ---------------------------------------------------------------------------
// Kernel 1: x = lrelu(bn(concat(noise, emb[label]) @ Wd)); write into g_x2
// channels [0,256); also write label-embedding channels [256,306).
// grid (49 pos, 16 b-tiles), 256 threads (one output channel each), 32 samples
// per block held in register accumulators.
// ---------------------------------------------------------------------------
__global__ void __launch_bounds__(256) dense_kernel(
    const float* __restrict__ noise, const int* __restrict__ labels,
    const float* __restrict__ emb,   const float* __restrict__ Wd,
    const float* __restrict__ g1, const float* __restrict__ b1,
    const float* __restrict__ m1, const float* __restrict__ v1)
{
    __shared__ float xin[150 * 32];            // [k][i] layout
    const int pos = blockIdx.x;                // 0..48
    const int bt  = blockIdx.y;                // 0..15
    const int tid = threadIdx.x;

    for (int idx = tid; idx < 32 * 150; idx += 256) {
        int i = idx / 150, k = idx - i * 150;
        int b = bt * 32 + i;
        float v = (k < NNOI) ? noise[b * NNOI + k]
                             : emb[labels[b] * NEMB + (k - NNOI)];
        xin[k * 32 + i] = v;
    }
    __syncthreads();

    const int ch = tid;
    const int j  = pos * C1 + ch;              // 0..12543
    float acc[32];
#pragma unroll
    for (int i = 0; i < 32; i++) acc[i] = 0.f;

    for (int k = 0; k < 150; k++) {
        float w = Wd[k * 12544 + j];
        const float4* xr = (const float4*)&xin[k * 32];
#pragma unroll
        for (int q = 0; q < 8; q++) {
            float4 xv = xr[q];
            acc[4*q+0] += xv.x * w;
            acc[4*q+1] += xv.y * w;
            acc[4*q+2] += xv.z * w;
            acc[4*q+3] += xv.w * w;
        }
    }

    const float sc = g1[j] * rsqrtf(v1[j] + BN_EPS);
    const float mm = m1[j], be = b1[j];
#pragma unroll
    for (int i = 0; i < 32; i++) {
        int b = bt * 32 + i;
        g_x2[((size_t)b * 49 + pos) * CIN1 + ch] = lrelu((acc[i] - mm) * sc + be);
    }
    if (ch < NEMB) {
#pragma unroll
        for (int i = 0; i < 32; i++) {
            int b = bt * 32 + i;
            g_x2[((size_t)b * 49 + pos) * CIN1 + C1 + ch] = xin[(NNOI + ch) * 32 + i];
        }
    }
}

// ---------------------------------------------------------------------------
// Kernel 2: ConvT1 (5x5 stride 1, SAME -> pad (2,2), unflipped HWIO kernel),
// 306 -> 256 on 7x7, per-sample class weights, + BN + lrelu.
// One block per sample, 256 threads (one out channel each), 49 accumulators.
// SMEM holds sample activations transposed [ci][52-padded pos].
// ---------------------------------------------------------------------------
__global__ void __launch_bounds__(256) conv1_kernel(
    const int* __restrict__ labels, const float* __restrict__ K1,
    const float* __restrict__ G1, const float* __restrict__ B1,
    const float* __restrict__ M1, const float* __restrict__ V1)
{
    extern __shared__ float xs[];              // [306][52]
    const int b  = blockIdx.x;
    const int c  = labels[b];
    const int co = threadIdx.x;

    const float* xg = &g_x2[(size_t)b * 49 * CIN1];
    for (int i = co; i < 49 * CIN1; i += 256) {
        int pos = i / CIN1, ci = i - pos * CIN1;
        xs[ci * 52 + pos] = xg[i];             // stride-49 scatter: conflict-free (odd)
    }
    __syncthreads();

    float acc[49];
#pragma unroll
    for (int p = 0; p < 49; p++) acc[p] = 0.f;

    const float* Wc = K1 + (size_t)c * 25 * CIN1 * C1 + co;

    for (int ci = 0; ci < CIN1; ci++) {
        float4 xv4[13];
#pragma unroll
        for (int q = 0; q < 13; q++) xv4[q] = *(const float4*)&xs[ci * 52 + 4 * q];
        const float* xv = (const float*)xv4;

        float w[25];
#pragma unroll
        for (int t = 0; t < 25; t++) w[t] = Wc[(t * CIN1 + ci) * C1];

#pragma unroll
        for (int ky = 0; ky < 5; ky++)
#pragma unroll
        for (int oy = 0; oy < 7; oy++) {
            int iy = oy + ky - 2;
            if (iy < 0 || iy >= 7) continue;
#pragma unroll
            for (int kx = 0; kx < 5; kx++)
#pragma unroll
            for (int ox = 0; ox < 7; ox++) {
                int ix = ox + kx - 2;
                if (ix < 0 || ix >= 7) continue;
                acc[oy * 7 + ox] += xv[iy * 7 + ix] * w[ky * 5 + kx];
            }
        }
    }

    const float sc = G1[c * C1 + co] * rsqrtf(V1[c * C1 + co] + BN_EPS);
    const float mm = M1[c * C1 + co], be = B1[c * C1 + co];
    float* hg = &g_h1[(size_t)b * 49 * C1 + co];
#pragma unroll
    for (int p = 0; p < 49; p++)
        hg[p * C1] = lrelu((acc[p] - mm) * sc + be);
}

// ---------------------------------------------------------------------------
// Kernel 3: ConvT2 (5x5 stride 2, SAME -> pad (3,2)), 256 -> 128, 7x7 -> 14x14,
// decomposed into 4 parity sub-convolutions. One block per sample, 128 threads.
//   oy = 2*my + PY; tap valid iff (PY+ky-3) even; iy = my + (PY+ky-3)/2
// ---------------------------------------------------------------------------
template<int PY, int PX>
__device__ __forceinline__ void conv2_phase(
    const float* xs, const float* Wc, float sc, float mm, float be, float* out)
{
    float acc[49];
#pragma unroll
    for (int p = 0; p < 49; p++) acc[p] = 0.f;

    for (int ci = 0; ci < C1; ci++) {
        float4 xv4[13];
#pragma unroll
        for (int q = 0; q < 13; q++) xv4[q] = *(const float4*)&xs[ci * 52 + 4 * q];
        const float* xv = (const float*)xv4;

        float w[25];
#pragma unroll
        for (int ky = 0; ky < 5; ky++)
#pragma unroll
        for (int kx = 0; kx < 5; kx++) {
            if (((PY + ky - 3) & 1) || ((PX + kx - 3) & 1)) continue;
            w[ky * 5 + kx] = Wc[((ky * 5 + kx) * C1 + ci) * C2];
        }

#pragma unroll
        for (int ky = 0; ky < 5; ky++) {
            if ((PY + ky - 3) & 1) continue;
#pragma unroll
            for (int my = 0; my < 7; my++) {
                int iy = my + (PY + ky - 3) / 2;
                if (iy < 0 || iy >= 7) continue;
#pragma unroll
                for (int kx = 0; kx < 5; kx++) {
                    if ((PX + kx - 3) & 1) continue;
#pragma unroll
                    for (int mx = 0; mx < 7; mx++) {
                        int ix = mx + (PX + kx - 3) / 2;
                        if (ix < 0 || ix >= 7) continue;
                        acc[my * 7 + mx] += xv[iy * 7 + ix] * w[ky * 5 + kx];
                    }
                }
            }
        }
    }

#pragma unroll
    for (int my = 0; my < 7; my++)
#pragma unroll
    for (int mx = 0; mx < 7; mx++) {
        int oy = 2 * my + PY, ox = 2 * mx + PX;
        out[(oy * 14 + ox) * C2] = lrelu((acc[my * 7 + mx] - mm) * sc + be);
    }
}

__global__ void __launch_bounds__(128) conv2_kernel(
    const int* __restrict__ labels, const float* __restrict__ K2,
    const float* __restrict__ G2, const float* __restrict__ B2,
    const float* __restrict__ M2, const float* __restrict__ V2)
{
    extern __shared__ float xs[];              // [256][52]
    const int b  = blockIdx.x;
    const int c  = labels[b];
    const int co = threadIdx.x;

    const float* hg = &g_h1[(size_t)b * 49 * C1];
    for (int i = co; i < 49 * C1; i += 128) {
        int pos = i >> 8, ci = i & 255;
        xs[ci * 52 + pos] = hg[i];
    }
    __syncthreads();

    const float sc = G2[c * C2 + co] * rsqrtf(V2[c * C2 + co] + BN_EPS);
    const float mm = M2[c * C2 + co], be = B2[c * C2 + co];
    const float* Wc = K2 + (size_t)c * 25 * C1 * C2 + co;
    float* out = &g_h2[(size_t)b * 196 * C2 + co];

    conv2_phase<0, 0>(xs, Wc, sc, mm, be, out);
    conv2_phase<0, 1>(xs, Wc, sc, mm, be, out);
    conv2_phase<1, 0>(xs, Wc, sc, mm, be, out);
    conv2_phase<1, 1>(xs, Wc, sc, mm, be, out);
}

// ---------------------------------------------------------------------------
// Kernel 4: ConvT3 (5x5 stride 2, pad (3,2)), 128 -> 1, 14x14 -> 28x28, tanh.
// One block per sample, 256 threads over 784 output pixels, vectorized ci dot.
// ---------------------------------------------------------------------------
__global__ void __launch_bounds__(256) conv3_kernel(
    const int* __restrict__ labels, const float* __restrict__ K3,
    float* __restrict__ out)
{
    extern __shared__ float smem[];
    float* h2s = smem;                          // 196*128
    float* Ks  = smem + 196 * C2;               // 25*128
    const int b   = blockIdx.x;
    const int c   = labels[b];
    const int tid = threadIdx.x;

    const float* hg = &g_h2[(size_t)b * 196 * C2];
    for (int i = tid; i < 196 * C2; i += 256) h2s[i] = hg[i];
    const float* Wc = K3 + c * 25 * C2;
    for (int i = tid; i < 25 * C2; i += 256) Ks[i] = Wc[i];
    __syncthreads();

    for (int pp = tid; pp < 784; pp += 256) {
        int oy = pp / 28, ox = pp - oy * 28;
        int py = oy & 1, px = ox & 1;
        int my = oy >> 1, mx = ox >> 1;
        float acc = 0.f;
        for (int ky = 0; ky < 5; ky++) {
            int dy = py + ky - 3;
            if (dy & 1) continue;
            int iy = my + (dy >> 1);
            if (iy < 0 || iy >= 14) continue;
            for (int kx = 0; kx < 5; kx++) {
                int dx = px + kx - 3;
                if (dx & 1) continue;
                int ix = mx + (dx >> 1);
                if (ix < 0 || ix >= 14) continue;
                const float4* hp = (const float4*)&h2s[(iy * 14 + ix) * C2];
                const float4* wp = (const float4*)&Ks[(ky * 5 + kx) * C2];
#pragma unroll 8
                for (int q = 0; q < 32; q++) {
                    float4 hv = hp[q], wv = wp[q];
                    acc += hv.x * wv.x + hv.y * wv.y + hv.z * wv.z + hv.w * wv.w;
                }
            }
        }
        out[(size_t)b * 784 + pp] = tanhf(acc);
    }
}

// ---------------------------------------------------------------------------
extern "C" void kernel_launch(void* const* d_in, const int* in_sizes, int n_in,
                              void* d_out, int out_size)
{
    const float* noise  = (const float*)d_in[0];
    const int*   labels = (const int*)  d_in[1];
    const float* emb    = (const float*)d_in[2];
    const float* Wd     = (const float*)d_in[3];
    const float* g1 = (const float*)d_in[4];
    const float* b1 = (const float*)d_in[5];
    const float* m1 = (const float*)d_in[6];
    const float* v1 = (const float*)d_in[7];
    const float* K1 = (const float*)d_in[8];
    const float* G1 = (const float*)d_in[9];
    const float* B1 = (const float*)d_in[10];
    const float* M1 = (const float*)d_in[11];
    const float* V1 = (const float*)d_in[12];
    const float* K2 = (const float*)d_in[13];
    const float* G2 = (const float*)d_in[14];
    const float* B2 = (const float*)d_in[15];
    const float* M2 = (const float*)d_in[16];
    const float* V2 = (const float*)d_in[17];
    const float* K3 = (const float*)d_in[18];
    float* out = (float*)d_out;

    const int smem1 = 306 * 52 * 4;                 // 63,648 B
    const int smem2 = 256 * 52 * 4;                 // 53,248 B
    const int smem3 = (196 * 128 + 25 * 128) * 4;   // 113,152 B
    cudaFuncSetAttribute(conv1_kernel, cudaFuncAttributeMaxDynamicSharedMemorySize, smem1);
    cudaFuncSetAttribute(conv2_kernel, cudaFuncAttributeMaxDynamicSharedMemorySize, smem2);
    cudaFuncSetAttribute(conv3_kernel, cudaFuncAttributeMaxDynamicSharedMemorySize, smem3);

    dense_kernel<<<dim3(49, 16), 256>>>(noise, labels, emb, Wd, g1, b1, m1, v1);
    conv1_kernel<<<NB, 256, smem1>>>(labels, K1, G1, B1, M1, V1);
    conv2_kernel<<<NB, 128, smem2>>>(labels, K2, G2, B2, M2, V2);
    conv3_kernel<<<NB, 256, smem3>>>(labels, K3, out);
}

// round 2
// speedup vs baseline: 1.0016x; 1.0016x over previous
#include <cuda_runtime.h>
#include <math.h>

#define NB    512
#define NNOI  100
#define NC    10
#define NEMB  50
#define CIN1  306      // 256 + NEMB
#define C1    256
#define C2    128
#define LRA   0.3f
#define BN_EPS 1e-3f

// scratch (static device globals; no runtime allocation)
__device__ float g_x2[(size_t)NB * 49 * CIN1];   // [b][pos=7*7][ci]
__device__ float g_h1[(size_t)NB * 49 * C1];     // [b][pos][co]
__device__ float g_h2[(size_t)NB * 196 * C2];    // [b][oy14][ox14][co]

__device__ __forceinline__ float lrelu(float x) { return x >= 0.f ? x : LRA * x; }

// ---------------------------------------------------------------------------
// Kernel 1: x = lrelu(bn(concat(noise, emb[label]) @ Wd)); write into g_x2
// channels [0,256); also write label-embedding channels [256,306).
// grid (49 pos, 16 b-tiles), 256 threads (one output channel each), 32 samples
// per block held in register accumulators.
// ---------------------------------------------------------------------------
__global__ void __launch_bounds__(256) dense_kernel(
    const float* __restrict__ noise, const int* __restrict__ labels,
    const float* __restrict__ emb,   const float* __restrict__ Wd,
    const float* __restrict__ g1, const float* __restrict__ b1,
    const float* __restrict__ m1, const float* __restrict__ v1)
{
    __shared__ float xin[150 * 32];            // [k][i] layout
    const int pos = blockIdx.x;                // 0..48
    const int bt  = blockIdx.y;                // 0..15
    const int tid = threadIdx.x;

    for (int idx = tid; idx < 32 * 150; idx += 256) {
        int i = idx / 150, k = idx - i * 150;
        int b = bt * 32 + i;
        float v = (k < NNOI) ? noise[b * NNOI + k]
                             : emb[labels[b] * NEMB + (k - NNOI)];
        xin[k * 32 + i] = v;
    }
    __syncthreads();

    const int ch = tid;
    const int j  = pos * C1 + ch;              // 0..12543
    float acc[32];
#pragma unroll
    for (int i = 0; i < 32; i++) acc[i] = 0.f;

    for (int k = 0; k < 150; k++) {
        float w = Wd[k * 12544 + j];
        const float4* xr = (const float4*)&xin[k * 32];
#pragma unroll
        for (int q = 0; q < 8; q++) {
            float4 xv = xr[q];
            acc[4*q+0] += xv.x * w;
            acc[4*q+1] += xv.y * w;
            acc[4*q+2] += xv.z * w;
            acc[4*q+3] += xv.w * w;
        }
    }

    const float sc = g1[j] * rsqrtf(v1[j] + BN_EPS);
    const float mm = m1[j], be = b1[j];
#pragma unroll
    for (int i = 0; i < 32; i++) {
        int b = bt * 32 + i;
        g_x2[((size_t)b * 49 + pos) * CIN1 + ch] = lrelu((acc[i] - mm) * sc + be);
    }
    if (ch < NEMB) {
#pragma unroll
        for (int i = 0; i < 32; i++) {
            int b = bt * 32 + i;
            g_x2[((size_t)b * 49 + pos) * CIN1 + C1 + ch] = xin[(NNOI + ch) * 32 + i];
        }
    }
}

// ---------------------------------------------------------------------------
// Kernel 2: ConvT1 (5x5 stride 1, SAME -> pad (2,2), unflipped HWIO kernel),
// 306 -> 256 on 7x7, per-sample class weights, + BN + lrelu.
// One block per sample, 256 threads (one out channel each), 49 accumulators.
// SMEM holds sample activations transposed [ci][52-padded pos].
// ---------------------------------------------------------------------------
__global__ void __launch_bounds__(256) conv1_kernel(
    const int* __restrict__ labels, const float* __restrict__ K1,
    const float* __restrict__ G1, const float* __restrict__ B1,
    const float* __restrict__ M1, const float* __restrict__ V1)
{
    extern __shared__ float xs[];              // [306][52]
    const int b  = blockIdx.x;
    const int c  = labels[b];
    const int co = threadIdx.x;

    const float* xg = &g_x2[(size_t)b * 49 * CIN1];
    for (int i = co; i < 49 * CIN1; i += 256) {
        int pos = i / CIN1, ci = i - pos * CIN1;
        xs[ci * 52 + pos] = xg[i];             // stride-49 scatter: conflict-free (odd)
    }
    __syncthreads();

    float acc[49];
#pragma unroll
    for (int p = 0; p < 49; p++) acc[p] = 0.f;

    const float* Wc = K1 + (size_t)c * 25 * CIN1 * C1 + co;

    for (int ci = 0; ci < CIN1; ci++) {
        float4 xv4[13];
#pragma unroll
        for (int q = 0; q < 13; q++) xv4[q] = *(const float4*)&xs[ci * 52 + 4 * q];
        const float* xv = (const float*)xv4;

        float w[25];
#pragma unroll
        for (int t = 0; t < 25; t++) w[t] = Wc[(t * CIN1 + ci) * C1];

#pragma unroll
        for (int ky = 0; ky < 5; ky++)
#pragma unroll
        for (int oy = 0; oy < 7; oy++) {
            int iy = oy + ky - 2;
            if (iy < 0 || iy >= 7) continue;
#pragma unroll
            for (int kx = 0; kx < 5; kx++)
#pragma unroll
            for (int ox = 0; ox < 7; ox++) {
                int ix = ox + kx - 2;
                if (ix < 0 || ix >= 7) continue;
                acc[oy * 7 + ox] += xv[iy * 7 + ix] * w[ky * 5 + kx];
            }
        }
    }

    const float sc = G1[c * C1 + co] * rsqrtf(V1[c * C1 + co] + BN_EPS);
    const float mm = M1[c * C1 + co], be = B1[c * C1 + co];
    float* hg = &g_h1[(size_t)b * 49 * C1 + co];
#pragma unroll
    for (int p = 0; p < 49; p++)
        hg[p * C1] = lrelu((acc[p] - mm) * sc + be);
}

// ---------------------------------------------------------------------------
// Kernel 3: ConvT2 (5x5 stride 2, SAME -> pad (3,2)), 256 -> 128, 7x7 -> 14x14,
// decomposed into 4 parity sub-convolutions. One block per sample, 128 threads.
//   oy = 2*my + PY; tap valid iff (PY+ky-3) even; iy = my + (PY+ky-3)/2
// ---------------------------------------------------------------------------
template<int PY, int PX>
__device__ __forceinline__ void conv2_phase(
    const float* xs, const float* Wc, float sc, float mm, float be, float* out)
{
    float acc[49];
#pragma unroll
    for (int p = 0; p < 49; p++) acc[p] = 0.f;

    for (int ci = 0; ci < C1; ci++) {
        float4 xv4[13];
#pragma unroll
        for (int q = 0; q < 13; q++) xv4[q] = *(const float4*)&xs[ci * 52 + 4 * q];
        const float* xv = (const float*)xv4;

        float w[25];
#pragma unroll
        for (int ky = 0; ky < 5; ky++)
#pragma unroll
        for (int kx = 0; kx < 5; kx++) {
            if (((PY + ky - 3) & 1) || ((PX + kx - 3) & 1)) continue;
            w[ky * 5 + kx] = Wc[((ky * 5 + kx) * C1 + ci) * C2];
        }

#pragma unroll
        for (int ky = 0; ky < 5; ky++) {
            if ((PY + ky - 3) & 1) continue;
#pragma unroll
            for (int my = 0; my < 7; my++) {
                int iy = my + (PY + ky - 3) / 2;
                if (iy < 0 || iy >= 7) continue;
#pragma unroll
                for (int kx = 0; kx < 5; kx++) {
                    if ((PX + kx - 3) & 1) continue;
#pragma unroll
                    for (int mx = 0; mx < 7; mx++) {
                        int ix = mx + (PX + kx - 3) / 2;
                        if (ix < 0 || ix >= 7) continue;
                        acc[my * 7 + mx] += xv[iy * 7 + ix] * w[ky * 5 + kx];
                    }
                }
            }
        }
    }

#pragma unroll
    for (int my = 0; my < 7; my++)
#pragma unroll
    for (int mx = 0; mx < 7; mx++) {
        int oy = 2 * my + PY, ox = 2 * mx + PX;
        out[(oy * 14 + ox) * C2] = lrelu((acc[my * 7 + mx] - mm) * sc + be);
    }
}

__global__ void __launch_bounds__(128) conv2_kernel(
    const int* __restrict__ labels, const float* __restrict__ K2,
    const float* __restrict__ G2, const float* __restrict__ B2,
    const float* __restrict__ M2, const float* __restrict__ V2)
{
    extern __shared__ float xs[];              // [256][52]
    const int b  = blockIdx.x;
    const int c  = labels[b];
    const int co = threadIdx.x;

    const float* hg = &g_h1[(size_t)b * 49 * C1];
    for (int i = co; i < 49 * C1; i += 128) {
        int pos = i >> 8, ci = i & 255;
        xs[ci * 52 + pos] = hg[i];
    }
    __syncthreads();

    const float sc = G2[c * C2 + co] * rsqrtf(V2[c * C2 + co] + BN_EPS);
    const float mm = M2[c * C2 + co], be = B2[c * C2 + co];
    const float* Wc = K2 + (size_t)c * 25 * C1 * C2 + co;
    float* out = &g_h2[(size_t)b * 196 * C2 + co];

    conv2_phase<0, 0>(xs, Wc, sc, mm, be, out);
    conv2_phase<0, 1>(xs, Wc, sc, mm, be, out);
    conv2_phase<1, 0>(xs, Wc, sc, mm, be, out);
    conv2_phase<1, 1>(xs, Wc, sc, mm, be, out);
}

// ---------------------------------------------------------------------------
// Kernel 4: ConvT3 (5x5 stride 2, pad (3,2)), 128 -> 1, 14x14 -> 28x28, tanh.
// One block per sample, 256 threads over 784 output pixels, vectorized ci dot.
// ---------------------------------------------------------------------------
__global__ void __launch_bounds__(256) conv3_kernel(
    const int* __restrict__ labels, const float* __restrict__ K3,
    float* __restrict__ out)
{
    extern __shared__ float smem[];
    float* h2s = smem;                          // 196*128
    float* Ks  = smem + 196 * C2;               // 25*128
    const int b   = blockIdx.x;
    const int c   = labels[b];
    const int tid = threadIdx.x;

    const float* hg = &g_h2[(size_t)b * 196 * C2];
    for (int i = tid; i < 196 * C2; i += 256) h2s[i] = hg[i];
    const float* Wc = K3 + c * 25 * C2;
    for (int i = tid; i < 25 * C2; i += 256) Ks[i] = Wc[i];
    __syncthreads();

    for (int pp = tid; pp < 784; pp += 256) {
        int oy = pp / 28, ox = pp - oy * 28;
        int py = oy & 1, px = ox & 1;
        int my = oy >> 1, mx = ox >> 1;
        float acc = 0.f;
        for (int ky = 0; ky < 5; ky++) {
            int dy = py + ky - 3;
            if (dy & 1) continue;
            int iy = my + (dy >> 1);
            if (iy < 0 || iy >= 14) continue;
            for (int kx = 0; kx < 5; kx++) {
                int dx = px + kx - 3;
                if (dx & 1) continue;
                int ix = mx + (dx >> 1);
                if (ix < 0 || ix >= 14) continue;
                const float4* hp = (const float4*)&h2s[(iy * 14 + ix) * C2];
                const float4* wp = (const float4*)&Ks[(ky * 5 + kx) * C2];
#pragma unroll 8
                for (int q = 0; q < 32; q++) {
                    float4 hv = hp[q], wv = wp[q];
                    acc += hv.x * wv.x + hv.y * wv.y + hv.z * wv.z + hv.w * wv.w;
                }
            }
        }
        out[(size_t)b * 784 + pp] = tanhf(acc);
    }
}

// ---------------------------------------------------------------------------
extern "C" void kernel_launch(void* const* d_in, const int* in_sizes, int n_in,
                              void* d_out, int out_size)
{
    const float* noise  = (const float*)d_in[0];
    const int*   labels = (const int*)  d_in[1];
    const float* emb    = (const float*)d_in[2];
    const float* Wd     = (const float*)d_in[3];
    const float* g1 = (const float*)d_in[4];
    const float* b1 = (const float*)d_in[5];
    const float* m1 = (const float*)d_in[6];
    const float* v1 = (const float*)d_in[7];
    const float* K1 = (const float*)d_in[8];
    const float* G1 = (const float*)d_in[9];
    const float* B1 = (const float*)d_in[10];
    const float* M1 = (const float*)d_in[11];
    const float* V1 = (const float*)d_in[12];
    const float* K2 = (const float*)d_in[13];
    const float* G2 = (const float*)d_in[14];
    const float* B2 = (const float*)d_in[15];
    const float* M2 = (const float*)d_in[16];
    const float* V2 = (const float*)d_in[17];
    const float* K3 = (const float*)d_in[18];
    float* out = (float*)d_out;

    const int smem1 = 306 * 52 * 4;                 // 63,648 B
    const int smem2 = 256 * 52 * 4;                 // 53,248 B
    const int smem3 = (196 * 128 + 25 * 128) * 4;   // 113,152 B
    cudaFuncSetAttribute(conv1_kernel, cudaFuncAttributeMaxDynamicSharedMemorySize, smem1);
    cudaFuncSetAttribute(conv2_kernel, cudaFuncAttributeMaxDynamicSharedMemorySize, smem2);
    cudaFuncSetAttribute(conv3_kernel, cudaFuncAttributeMaxDynamicSharedMemorySize, smem3);

    dense_kernel<<<dim3(49, 16), 256>>>(noise, labels, emb, Wd, g1, b1, m1, v1);
    conv1_kernel<<<NB, 256, smem1>>>(labels, K1, G1, B1, M1, V1);
    conv2_kernel<<<NB, 128, smem2>>>(labels, K2, G2, B2, M2, V2);
    conv3_kernel<<<NB, 256, smem3>>>(labels, K3, out);
}